// round 7
// baseline (speedup 1.0000x reference)
#include <cuda_runtime.h>
#include <cuda_bf16.h>
#include <math.h>
#include <cstdint>

#define BB 64
#define TT 1024
#define DD 256
#define HH 128
#define G4 512           // 4*H gate width
#define NTAGS 3
#define M_TOTAL (BB*TT)  // 65536

typedef unsigned long long u64;

// single dynamic-shared extern for all kernels
extern __shared__ char smem_raw[];

// ---------------- static scratch (no allocs allowed) ----------------
__device__ float g_gx[(size_t)2 * BB * TT * G4];        // [dir][b][t][512]
__device__ float g_seq1[(size_t)BB * TT * 2 * HH];      // layer1 output (fp32 for emissions)
__device__ float g_part[BB];
__device__ __nv_bfloat16 g_xhi[(size_t)M_TOTAL * DD];   // A hi
__device__ __nv_bfloat16 g_xlo[(size_t)M_TOTAL * DD];   // A lo
__device__ __nv_bfloat16 g_whi[(size_t)2 * G4 * DD];    // W hi (2 dirs)
__device__ __nv_bfloat16 g_wlo[(size_t)2 * G4 * DD];    // W lo

// fast sigmoid / tanh (err ~2^-20)
__device__ __forceinline__ float fsig(float x) {
    return __fdividef(1.0f, 1.0f + __expf(-x));
}
__device__ __forceinline__ float ftanh_id(float x) {   // 2*sig(2x)-1
    return fmaf(2.0f, __fdividef(1.0f, 1.0f + __expf(-2.0f * x)), -1.0f);
}

// ---- packed f32x2 helpers ----
__device__ __forceinline__ void fma2(u64& d, u64 a, u64 b) {
    asm("fma.rn.f32x2 %0, %1, %2, %0;" : "+l"(d) : "l"(a), "l"(b));
}
__device__ __forceinline__ void add2(u64& d, u64 a, u64 b) {
    asm("add.rn.f32x2 %0, %1, %2;" : "=l"(d) : "l"(a), "l"(b));
}
__device__ __forceinline__ float2 unpk(u64 v) {
    float2 f; asm("mov.b64 {%0, %1}, %2;" : "=f"(f.x), "=f"(f.y) : "l"(v)); return f;
}

__device__ __forceinline__ uint32_t smem_u32(const void* p) {
    uint32_t a;
    asm("{ .reg .u64 t; cvta.to.shared.u64 t, %1; cvt.u32.u64 %0, t; }" : "=r"(a) : "l"(p));
    return a;
}

// ---- ldmatrix / mma.sync / cp.async (base sm_80+ ISA) ----
__device__ __forceinline__ void ldm_x4(uint32_t* r, uint32_t addr) {
    asm volatile("ldmatrix.sync.aligned.m8n8.x4.shared.b16 {%0,%1,%2,%3}, [%4];"
        : "=r"(r[0]), "=r"(r[1]), "=r"(r[2]), "=r"(r[3]) : "r"(addr));
}
__device__ __forceinline__ void mma_bf16(float* d, const uint32_t* a, uint32_t b0, uint32_t b1) {
    asm volatile("mma.sync.aligned.m16n8k16.row.col.f32.bf16.bf16.f32 "
        "{%0,%1,%2,%3}, {%4,%5,%6,%7}, {%8,%9}, {%0,%1,%2,%3};"
        : "+f"(d[0]), "+f"(d[1]), "+f"(d[2]), "+f"(d[3])
        : "r"(a[0]), "r"(a[1]), "r"(a[2]), "r"(a[3]), "r"(b0), "r"(b1));
}
__device__ __forceinline__ void cpa16(uint32_t dst, const void* src) {
    asm volatile("cp.async.cg.shared.global [%0], [%1], 16;" :: "r"(dst), "l"(src));
}

// =====================================================================
// fp32 -> bf16 hi/lo split (vectorized x4)
// =====================================================================
__global__ void cvt_hilo_kernel(const float* __restrict__ s,
                                __nv_bfloat16* __restrict__ hi,
                                __nv_bfloat16* __restrict__ lo, int n4)
{
    int i = blockIdx.x * 256 + threadIdx.x;
    if (i >= n4) return;
    float4 v = ((const float4*)s)[i];
    __nv_bfloat16 h0 = __float2bfloat16(v.x), h1 = __float2bfloat16(v.y);
    __nv_bfloat16 h2 = __float2bfloat16(v.z), h3 = __float2bfloat16(v.w);
    __nv_bfloat162* hp = (__nv_bfloat162*)hi;
    hp[i * 2]     = __nv_bfloat162{h0, h1};
    hp[i * 2 + 1] = __nv_bfloat162{h2, h3};
    __nv_bfloat162* lp = (__nv_bfloat162*)lo;
    lp[i * 2]     = __nv_bfloat162{__float2bfloat16(v.x - __bfloat162float(h0)),
                                   __float2bfloat16(v.y - __bfloat162float(h1))};
    lp[i * 2 + 1] = __nv_bfloat162{__float2bfloat16(v.z - __bfloat162float(h2)),
                                   __float2bfloat16(v.w - __bfloat162float(h3))};
}

// =====================================================================
// bf16x3 GEMM via mma.sync m16n8k16 + 2-stage cp.async pipeline.
// (unchanged from round 6)
// =====================================================================
#define KC    64
#define AROW  72                 // KC + 8 pad (bf16 elems)
#define TILEB (128 * AROW * 2)
#define STAGEB (2 * TILEB)
#define GEMM_SMEM (2 * STAGEB)   // 73728

__global__ __launch_bounds__(256, 2)
void gemm_mma_kernel(const __nv_bfloat16* __restrict__ xhi,
                     const __nv_bfloat16* __restrict__ xlo,
                     const __nv_bfloat16* __restrict__ whi,
                     const __nv_bfloat16* __restrict__ wlo,
                     const float* __restrict__ bihf, const float* __restrict__ bhhf,
                     const float* __restrict__ bihb, const float* __restrict__ bhhb,
                     float* __restrict__ gx)
{
    __shared__ float sbias[128];

    const int tid = threadIdx.x;
    const int lane = tid & 31;
    const int wid = tid >> 5;
    const int warp_m = wid >> 2;
    const int warp_n = wid & 3;
    const int m0 = blockIdx.y * 128;
    const int n0 = blockIdx.x * 128;
    const int dir = blockIdx.z;
    const __nv_bfloat16* Wh = whi + (size_t)dir * G4 * DD;
    const __nv_bfloat16* Wl = wlo + (size_t)dir * G4 * DD;
    const float* bih = dir ? bihb : bihf;
    const float* bhh = dir ? bhhb : bhhf;
    const uint32_t sdyn = smem_u32(smem_raw);

    if (tid < 128) sbias[tid] = bih[n0 + tid] + bhh[n0 + tid];

    float acc[4][4][4];
#pragma unroll
    for (int mt = 0; mt < 4; mt++)
#pragma unroll
        for (int nt = 0; nt < 4; nt++)
#pragma unroll
            for (int q = 0; q < 4; q++) acc[mt][nt][q] = 0.0f;

    uint32_t aOff[4], bOff[2];
#pragma unroll
    for (int mt = 0; mt < 4; mt++) {
        int row = warp_m * 64 + mt * 16 + (lane & 15);
        aOff[mt] = (uint32_t)((row * AROW + (lane >> 4) * 8) * 2);
    }
#pragma unroll
    for (int nh = 0; nh < 2; nh++) {
        int row = warp_n * 32 + nh * 16 + (lane & 15);
        bOff[nh] = (uint32_t)(TILEB + (row * AROW + (lane >> 4) * 8) * 2);
    }

    auto prefetch = [&](int c, int st) {
        const __nv_bfloat16* Asrc = (c >= 4 && c < 8) ? xlo : xhi;
        const __nv_bfloat16* Bsrc = (c >= 8) ? Wl : Wh;
        int kc = (c & 3) * KC;
        uint32_t base = sdyn + st * STAGEB;
#pragma unroll
        for (int i = 0; i < 4; i++) {
            int u = tid + i * 256;
            int row = u >> 3;
            int c8 = (u & 7) * 8;
            cpa16(base + (uint32_t)((row * AROW + c8) * 2),
                  Asrc + (size_t)(m0 + row) * DD + kc + c8);
            cpa16(base + (uint32_t)(TILEB + (row * AROW + c8) * 2),
                  Bsrc + (size_t)(n0 + row) * DD + kc + c8);
        }
        asm volatile("cp.async.commit_group;" ::: "memory");
    };

    prefetch(0, 0);
    for (int c = 0; c < 12; c++) {
        if (c + 1 < 12) {
            prefetch(c + 1, (c + 1) & 1);
            asm volatile("cp.async.wait_group 1;" ::: "memory");
        } else {
            asm volatile("cp.async.wait_group 0;" ::: "memory");
        }
        __syncthreads();

        uint32_t st = sdyn + (uint32_t)((c & 1) * STAGEB);
#pragma unroll
        for (int k16 = 0; k16 < KC / 16; k16++) {
            uint32_t a[4][4], b[2][4];
#pragma unroll
            for (int mt = 0; mt < 4; mt++)
                ldm_x4(a[mt], st + aOff[mt] + k16 * 32);
#pragma unroll
            for (int nh = 0; nh < 2; nh++)
                ldm_x4(b[nh], st + bOff[nh] + k16 * 32);
#pragma unroll
            for (int mt = 0; mt < 4; mt++)
#pragma unroll
                for (int nt = 0; nt < 4; nt++) {
                    int nh = nt >> 1, sub = nt & 1;
                    mma_bf16(acc[mt][nt], a[mt], b[nh][sub], b[nh][sub + 2]);
                }
        }
        __syncthreads();
    }

    float* gxd = gx + (size_t)dir * M_TOTAL * G4;
#pragma unroll
    for (int mt = 0; mt < 4; mt++) {
        int r0 = m0 + warp_m * 64 + mt * 16 + (lane >> 2);
#pragma unroll
        for (int nt = 0; nt < 4; nt++) {
            int cidx = warp_n * 32 + nt * 8 + (lane & 3) * 2;
            int col = n0 + cidx;
            float2 v0 = make_float2(acc[mt][nt][0] + sbias[cidx],
                                    acc[mt][nt][1] + sbias[cidx + 1]);
            float2 v1 = make_float2(acc[mt][nt][2] + sbias[cidx],
                                    acc[mt][nt][3] + sbias[cidx + 1]);
            *(float2*)(gxd + (size_t)r0 * G4 + col) = v0;
            *(float2*)(gxd + (size_t)(r0 + 8) * G4 + col) = v1;
        }
    }
}

// =====================================================================
// LSTM scan, quad-thread: 512 threads, one block per (dir,batch).
// Thread j: unit u = j>>2, gate g = j&3 (i,f,g,o) -> row = g*128+u.
// All 4 gates of a unit in one warp -> activation exchange via shfl.
// W_hh: KREG=88 cols in regs per row, KS=40 in smem.
// h double-buffered (fp32) -> ONE barrier per step.
// mode 0: write h as bf16 hi/lo into xhi/xlo (feeds layer-1 GEMM)
// mode 1: write h fp32 into outF (feeds emissions)
// =====================================================================
#define KREG 88
#define KS   40
#define NW16 (KS / 4)   // 10 ulonglong2 chunks per row
#define SCAN_SMEM (NW16 * 512 * 16 + 2 * HH * 4)   // 81920 + 1024 = 82944

__global__ __launch_bounds__(512, 1)
void lstm_scan_kernel(const float* __restrict__ gx,
                      const float* __restrict__ w_hh_f,
                      const float* __restrict__ w_hh_b,
                      float* __restrict__ outF,
                      __nv_bfloat16* __restrict__ outHi,
                      __nv_bfloat16* __restrict__ outLo,
                      int mode)
{
    float* smem = (float*)smem_raw;
    const int bid = blockIdx.x;     // 0..127
    const int dir = bid >> 6;
    const int b   = bid & 63;
    const int j   = threadIdx.x;    // 0..511
    const int lane = j & 31;
    const int gate = j & 3;         // 0=i,1=f,2=g,3=o
    const int unit = j >> 2;        // 0..127
    const int row  = gate * HH + unit;
    const float* W = dir ? w_hh_b : w_hh_f;

    ulonglong2* ws2 = (ulonglong2*)smem;            // [NW16][512]
    float* shb = smem + NW16 * 512 * 4;             // h double buffer [2][128]

    // weights: cols 0..KREG-1 in regs as u64 pairs
    u64 wr[KREG / 2];
    {
        const u64* wp = (const u64*)(W + (size_t)row * HH);
#pragma unroll
        for (int p = 0; p < KREG / 2; p++) wr[p] = wp[p];
    }
    // cols KREG..127 in smem
#pragma unroll
    for (int k2 = 0; k2 < NW16; k2++)
        ws2[k2 * 512 + j] = *(const ulonglong2*)(W + (size_t)row * HH + KREG + k2 * 4);

    if (j < HH) shb[j] = 0.0f;
    float c = 0.0f;

    // activation constants per gate: g-gate uses tanh = 2*sig(2x)-1
    const float scl = (gate == 2) ? 2.0f : 1.0f;
    const float mulp = (gate == 2) ? 2.0f : 1.0f;
    const float addp = (gate == 2) ? -1.0f : 0.0f;

    __syncthreads();

    const float* gxb = gx + ((size_t)dir * BB + b) * TT * G4;
    const int dt = dir ? -1 : 1;
    int tt = dir ? (TT - 1) : 0;
    float gcur = gxb[(size_t)tt * G4 + row];

    for (int t = 0; t < TT; t++) {
        int ttn = tt + dt;
        float gnext = (t < TT - 1) ? gxb[(size_t)ttn * G4 + row] : 0.0f;

        const float* sh = shb + ((t & 1) << 7);
        float* shw = shb + (((t + 1) & 1) << 7);

        u64 acca = 0ull, accb = 0ull;
#pragma unroll
        for (int p = 0; p < KREG / 2; p += 2) {
            ulonglong2 h2 = *(const ulonglong2*)(sh + p * 2);
            fma2(acca, wr[p],     h2.x);
            fma2(accb, wr[p + 1], h2.y);
        }
#pragma unroll
        for (int k2 = 0; k2 < NW16; k2++) {
            ulonglong2 w2 = ws2[k2 * 512 + j];
            ulonglong2 h2 = *(const ulonglong2*)(sh + KREG + k2 * 4);
            fma2(acca, w2.x, h2.x);
            fma2(accb, w2.y, h2.y);
        }
        u64 s01; add2(s01, acca, accb);
        float2 v = unpk(s01);
        float a = gcur + v.x + v.y;

        // per-gate activation
        float s = fsig(a * scl);
        float p = fmaf(mulp, s, addp);

        // gather f,g,o at the i-thread of each unit
        int base = lane & 28;
        float q1 = __shfl_sync(0xffffffffu, p, base | 1);
        float q2 = __shfl_sync(0xffffffffu, p, base | 2);
        float q3 = __shfl_sync(0xffffffffu, p, base | 3);

        if (gate == 0) {
            c = q1 * c + p * q2;            // f*c + i*g
            float h = q3 * ftanh_id(c);     // o*tanh(c)
            shw[unit] = h;
            size_t oidx = ((size_t)b * TT + tt) * DD + dir * HH + unit;
            if (mode == 0) {
                __nv_bfloat16 hh = __float2bfloat16(h);
                outHi[oidx] = hh;
                outLo[oidx] = __float2bfloat16(h - __bfloat162float(hh));
            } else {
                outF[oidx] = h;
            }
        }
        __syncthreads();

        gcur = gnext;
        tt = ttn;
    }
}

// =====================================================================
// Emissions: one warp per row.
// =====================================================================
__global__ void emissions_kernel(const float* __restrict__ seq,
                                 const float* __restrict__ fcw,
                                 const float* __restrict__ fcb,
                                 float* __restrict__ em)
{
    int gw = (int)((blockIdx.x * blockDim.x + threadIdx.x) >> 5);
    int lane = threadIdx.x & 31;
    if (gw >= M_TOTAL) return;
    const float* row = seq + (size_t)gw * 256 + lane * 8;
    float4 xa = *(const float4*)(row);
    float4 xb = *(const float4*)(row + 4);
#pragma unroll
    for (int tag = 0; tag < NTAGS; tag++) {
        const float* w = fcw + tag * 256 + lane * 8;
        float4 wa = *(const float4*)(w);
        float4 wb = *(const float4*)(w + 4);
        float p = xa.x * wa.x + xa.y * wa.y + xa.z * wa.z + xa.w * wa.w
                + xb.x * wb.x + xb.y * wb.y + xb.z * wb.z + xb.w * wb.w;
#pragma unroll
        for (int off = 16; off > 0; off >>= 1)
            p += __shfl_xor_sync(0xffffffffu, p, off);
        if (lane == 0) em[(size_t)gw * NTAGS + tag] = p + fcb[tag];
    }
}

// =====================================================================
// CRF
// =====================================================================
__global__ void crf_batch_kernel(const float* __restrict__ em,
                                 const int* __restrict__ tags,
                                 const float* __restrict__ startv,
                                 const float* __restrict__ endv,
                                 const float* __restrict__ trans,
                                 float* __restrict__ part)
{
    int b = blockIdx.x;
    int lane = threadIdx.x;
    const float* emb = em + (size_t)b * TT * NTAGS;
    const int* tg = tags + (size_t)b * TT;

    float s = 0.0f;
    for (int t = lane; t < TT; t += 32) {
        int tag = tg[t];
        s += emb[t * NTAGS + tag];
        if (t > 0) s += trans[tg[t - 1] * NTAGS + tag];
    }
#pragma unroll
    for (int off = 16; off > 0; off >>= 1)
        s += __shfl_xor_sync(0xffffffffu, s, off);

    float alpha = -1e30f;
    float tr0 = 0.f, tr1 = 0.f, tr2 = 0.f;
    if (lane < NTAGS) {
        alpha = startv[lane] + emb[lane];
        tr0 = trans[0 * NTAGS + lane];
        tr1 = trans[1 * NTAGS + lane];
        tr2 = trans[2 * NTAGS + lane];
    }
    for (int t = 1; t < TT; t++) {
        float a0 = __shfl_sync(0xffffffffu, alpha, 0);
        float a1 = __shfl_sync(0xffffffffu, alpha, 1);
        float a2 = __shfl_sync(0xffffffffu, alpha, 2);
        if (lane < NTAGS) {
            float v0 = a0 + tr0, v1 = a1 + tr1, v2 = a2 + tr2;
            float m = fmaxf(v0, fmaxf(v1, v2));
            alpha = emb[t * NTAGS + lane] + m +
                    logf(expf(v0 - m) + expf(v1 - m) + expf(v2 - m));
        }
    }
    if (lane < NTAGS) alpha += endv[lane];
    float a0 = __shfl_sync(0xffffffffu, alpha, 0);
    float a1 = __shfl_sync(0xffffffffu, alpha, 1);
    float a2 = __shfl_sync(0xffffffffu, alpha, 2);
    if (lane == 0) {
        float m = fmaxf(a0, fmaxf(a1, a2));
        float logZ = m + logf(expf(a0 - m) + expf(a1 - m) + expf(a2 - m));
        float num = s + startv[tg[0]] + endv[tg[TT - 1]];
        part[b] = num - logZ;
    }
}

__global__ void crf_reduce_kernel(const float* __restrict__ part, float* __restrict__ out)
{
    float s = 0.0f;
    for (int i = 0; i < BB; i++) s += part[i];
    out[0] = -s / (float)BB;
}

// =====================================================================
extern "C" void kernel_launch(void* const* d_in, const int* in_sizes, int n_in,
                              void* d_out, int out_size)
{
    const float* x         = (const float*)d_in[0];
    const int*   tags      = (const int*)  d_in[1];
    const float* w_ih_l0   = (const float*)d_in[2];
    const float* w_hh_l0   = (const float*)d_in[3];
    const float* b_ih_l0   = (const float*)d_in[4];
    const float* b_hh_l0   = (const float*)d_in[5];
    const float* w_ih_l0r  = (const float*)d_in[6];
    const float* w_hh_l0r  = (const float*)d_in[7];
    const float* b_ih_l0r  = (const float*)d_in[8];
    const float* b_hh_l0r  = (const float*)d_in[9];
    const float* w_ih_l1   = (const float*)d_in[10];
    const float* w_hh_l1   = (const float*)d_in[11];
    const float* b_ih_l1   = (const float*)d_in[12];
    const float* b_hh_l1   = (const float*)d_in[13];
    const float* w_ih_l1r  = (const float*)d_in[14];
    const float* w_hh_l1r  = (const float*)d_in[15];
    const float* b_ih_l1r  = (const float*)d_in[16];
    const float* b_hh_l1r  = (const float*)d_in[17];
    const float* fc_w      = (const float*)d_in[18];
    const float* fc_b      = (const float*)d_in[19];
    const float* crf_start = (const float*)d_in[20];
    const float* crf_end   = (const float*)d_in[21];
    const float* crf_trans = (const float*)d_in[22];

    float* out = (float*)d_out;

    float *gx, *seq1, *part;
    __nv_bfloat16 *xhi, *xlo, *whi, *wlo;
    cudaGetSymbolAddress((void**)&gx,   g_gx);
    cudaGetSymbolAddress((void**)&seq1, g_seq1);
    cudaGetSymbolAddress((void**)&part, g_part);
    cudaGetSymbolAddress((void**)&xhi,  g_xhi);
    cudaGetSymbolAddress((void**)&xlo,  g_xlo);
    cudaGetSymbolAddress((void**)&whi,  g_whi);
    cudaGetSymbolAddress((void**)&wlo,  g_wlo);

    cudaFuncSetAttribute(lstm_scan_kernel,
                         cudaFuncAttributeMaxDynamicSharedMemorySize, SCAN_SMEM);
    cudaFuncSetAttribute(gemm_mma_kernel,
                         cudaFuncAttributeMaxDynamicSharedMemorySize, GEMM_SMEM);

    const int NX4 = M_TOTAL * DD / 4;
    const int NW4 = G4 * DD / 4;
    dim3 ggrid(4, 512, 2);

    // ---- layer 0 ----
    cvt_hilo_kernel<<<(NX4 + 255) / 256, 256>>>(x, xhi, xlo, NX4);
    cvt_hilo_kernel<<<(NW4 + 255) / 256, 256>>>(w_ih_l0,  whi,            wlo,            NW4);
    cvt_hilo_kernel<<<(NW4 + 255) / 256, 256>>>(w_ih_l0r, whi + G4 * DD,  wlo + G4 * DD,  NW4);
    gemm_mma_kernel<<<ggrid, 256, GEMM_SMEM>>>(xhi, xlo, whi, wlo,
                                               b_ih_l0, b_hh_l0, b_ih_l0r, b_hh_l0r, gx);
    // scan layer 0: writes xhi/xlo (bf16 hi/lo) directly for layer-1 GEMM
    lstm_scan_kernel<<<128, 512, SCAN_SMEM>>>(gx, w_hh_l0, w_hh_l0r,
                                              (float*)nullptr, xhi, xlo, 0);

    // ---- layer 1 ----
    cvt_hilo_kernel<<<(NW4 + 255) / 256, 256>>>(w_ih_l1,  whi,            wlo,            NW4);
    cvt_hilo_kernel<<<(NW4 + 255) / 256, 256>>>(w_ih_l1r, whi + G4 * DD,  wlo + G4 * DD,  NW4);
    gemm_mma_kernel<<<ggrid, 256, GEMM_SMEM>>>(xhi, xlo, whi, wlo,
                                               b_ih_l1, b_hh_l1, b_ih_l1r, b_hh_l1r, gx);
    lstm_scan_kernel<<<128, 512, SCAN_SMEM>>>(gx, w_hh_l1, w_hh_l1r,
                                              seq1, (__nv_bfloat16*)nullptr,
                                              (__nv_bfloat16*)nullptr, 1);

    // ---- emissions + CRF ----
    emissions_kernel<<<(M_TOTAL * 32 + 255) / 256, 256>>>(seq1, fc_w, fc_b, out + 1);
    crf_batch_kernel<<<BB, 32>>>(out + 1, tags, crf_start, crf_end, crf_trans, part);
    crf_reduce_kernel<<<1, 1>>>(part, out);
}